// round 6
// baseline (speedup 1.0000x reference)
#include <cuda_runtime.h>
#include <float.h>

#define NB    4
#define NP    64
#define BP    256           // NB*NP query rows
#define D     768
#define NN    2048
#define RR    12
#define TOPK  16
#define KSPLIT 4

// ---- scratch (static __device__, no allocations) ----
__device__ float g_keys[NN * D];          // normalized keys      6.3 MB
__device__ float g_scores[BP * NN];       // scores               2.0 MB
__device__ int   g_idx[BP * TOPK];
__device__ float g_w[BP * TOPK];
__device__ float g_adjsum[NN * NN];       // sum_r adjacency     16.8 MB
__device__ float g_nei[BP * NN];          //                      2.0 MB
__device__ float g_part[KSPLIT][BP * D];  // split-K partials     3.1 MB

#define FMA_F32X2(d, a, b, c) \
    asm("fma.rn.f32x2 %0, %1, %2, %3;" : "=l"(d) : "l"(a), "l"(b), "l"(c))

// ---------------------------------------------------------------------------
// K1: row-normalize keys_param -> g_keys
// ---------------------------------------------------------------------------
__global__ void k_normalize(const float* __restrict__ kp) {
    int row = blockIdx.x;
    const float* src = kp + (long long)row * D;
    float ss = 0.f;
    for (int i = threadIdx.x; i < D; i += blockDim.x) { float v = src[i]; ss += v * v; }
    __shared__ float red[32];
    unsigned lane = threadIdx.x & 31, wid = threadIdx.x >> 5;
    #pragma unroll
    for (int o = 16; o; o >>= 1) ss += __shfl_down_sync(0xffffffff, ss, o);
    if (lane == 0) red[wid] = ss;
    __syncthreads();
    if (wid == 0) {
        ss = (lane < (blockDim.x >> 5)) ? red[lane] : 0.f;
        #pragma unroll
        for (int o = 16; o; o >>= 1) ss += __shfl_down_sync(0xffffffff, ss, o);
        if (lane == 0) red[0] = rsqrtf(ss + 1e-12f);
    }
    __syncthreads();
    float s = red[0];
    for (int i = threadIdx.x; i < D; i += blockDim.x)
        g_keys[(long long)row * D + i] = src[i] * s;
}

// ---------------------------------------------------------------------------
// K2: scores[m,n] = sum_d pos[m,d]*keys[n,d]  (NT), f32x2 FFMA2
// BM=64, BN=64, BK=16, 256 thr, 4x4 thread tile, A duplicated in smem
// ---------------------------------------------------------------------------
__global__ void k_scores(const float* __restrict__ pos) {
    __shared__ float Asd[16][132];   // duplicated pairs: Asd[k][2m]=Asd[k][2m+1]=A[m][k]
    __shared__ float Bs[16][68];
    int m0 = blockIdx.y * 64, n0 = blockIdx.x * 64;
    int t = threadIdx.x;
    int tx = t & 15, ty = t >> 4;        // tx: n-quad, ty: m-quad
    int am = t >> 2, aq = t & 3;         // loader mapping (64 rows x 4 quads)
    unsigned long long acc[4][2] = {};
    for (int k0 = 0; k0 < D; k0 += 16) {
        float4 av = *(const float4*)&pos[(long long)(m0 + am) * D + k0 + aq * 4];
        float2 d0 = {av.x, av.x}, d1 = {av.y, av.y}, d2 = {av.z, av.z}, d3 = {av.w, av.w};
        *(float2*)&Asd[aq * 4 + 0][2 * am] = d0;
        *(float2*)&Asd[aq * 4 + 1][2 * am] = d1;
        *(float2*)&Asd[aq * 4 + 2][2 * am] = d2;
        *(float2*)&Asd[aq * 4 + 3][2 * am] = d3;
        float4 bv = *(const float4*)&g_keys[(long long)(n0 + am) * D + k0 + aq * 4];
        Bs[aq * 4 + 0][am] = bv.x;
        Bs[aq * 4 + 1][am] = bv.y;
        Bs[aq * 4 + 2][am] = bv.z;
        Bs[aq * 4 + 3][am] = bv.w;
        __syncthreads();
        #pragma unroll
        for (int kk = 0; kk < 16; kk++) {
            ulonglong2 a01 = *(const ulonglong2*)&Asd[kk][ty * 8];
            ulonglong2 a23 = *(const ulonglong2*)&Asd[kk][ty * 8 + 4];
            ulonglong2 bb  = *(const ulonglong2*)&Bs[kk][tx * 4];
            FMA_F32X2(acc[0][0], a01.x, bb.x, acc[0][0]);
            FMA_F32X2(acc[0][1], a01.x, bb.y, acc[0][1]);
            FMA_F32X2(acc[1][0], a01.y, bb.x, acc[1][0]);
            FMA_F32X2(acc[1][1], a01.y, bb.y, acc[1][1]);
            FMA_F32X2(acc[2][0], a23.x, bb.x, acc[2][0]);
            FMA_F32X2(acc[2][1], a23.x, bb.y, acc[2][1]);
            FMA_F32X2(acc[3][0], a23.y, bb.x, acc[3][0]);
            FMA_F32X2(acc[3][1], a23.y, bb.y, acc[3][1]);
        }
        __syncthreads();
    }
    #pragma unroll
    for (int mm = 0; mm < 4; mm++) {
        float2 lo = *(float2*)&acc[mm][0];
        float2 hi = *(float2*)&acc[mm][1];
        float4 o = {lo.x, lo.y, hi.x, hi.y};
        *(float4*)&g_scores[(long long)(m0 + ty * 4 + mm) * NN + n0 + tx * 4] = o;
    }
}

// ---------------------------------------------------------------------------
// K3: block-per-row top-16 + softmax.
// Each warp: lane-sort-8 (Batcher) + 16 shfl-argmax pops -> warp top16.
// Warp 0 merges 8x16 candidates. Ties -> smaller index (matches lax.top_k).
// ---------------------------------------------------------------------------
__global__ void k_topk() {
    int row = blockIdx.x;
    int w = threadIdx.x >> 5, lane = threadIdx.x & 31;
    __shared__ float cv[8][TOPK];
    __shared__ int   ci[8][TOPK];
    __shared__ float rv_[TOPK];
    __shared__ int   ri_[TOPK];

    const float4* src = (const float4*)(g_scores + (long long)row * NN);
    float4 x = src[w * 64 + lane];
    float4 y = src[w * 64 + 32 + lane];
    int b0 = (w * 64 + lane) * 4, b1 = (w * 64 + 32 + lane) * 4;
    float v[8]  = {x.x, x.y, x.z, x.w, y.x, y.y, y.z, y.w};
    int   id[8] = {b0, b0 + 1, b0 + 2, b0 + 3, b1, b1 + 1, b1 + 2, b1 + 3};

    // descending sort, tie -> smaller index (19-CE Batcher network)
    #define CE(i, j) do {                                                 \
        float _av = v[i], _bv = v[j]; int _ai = id[i], _bi = id[j];       \
        bool _sw = (_bv > _av) || (_bv == _av && _bi < _ai);              \
        v[i]  = _sw ? _bv : _av;  id[i] = _sw ? _bi : _ai;                \
        v[j]  = _sw ? _av : _bv;  id[j] = _sw ? _ai : _bi;                \
    } while (0)
    CE(0,1); CE(2,3); CE(4,5); CE(6,7);
    CE(0,2); CE(1,3); CE(4,6); CE(5,7);
    CE(1,2); CE(5,6);
    CE(0,4); CE(1,5); CE(2,6); CE(3,7);
    CE(2,4); CE(3,5);
    CE(1,2); CE(3,4); CE(5,6);
    #undef CE

    // 16 pops: warp argmax over lane heads
    #pragma unroll 1
    for (int r = 0; r < TOPK; r++) {
        float wv = v[0]; int wi = id[0];
        #pragma unroll
        for (int o = 16; o; o >>= 1) {
            float ov = __shfl_xor_sync(0xffffffff, wv, o);
            int   oi = __shfl_xor_sync(0xffffffff, wi, o);
            if (ov > wv || (ov == wv && oi < wi)) { wv = ov; wi = oi; }
        }
        if (wi == id[0]) {                       // this lane owned the winner
            #pragma unroll
            for (int q = 0; q < 7; q++) { v[q] = v[q + 1]; id[q] = id[q + 1]; }
            v[7] = -FLT_MAX; id[7] = 1 << 30;
        }
        if (lane == 0) { cv[w][r] = wv; ci[w][r] = wi; }
    }
    __syncthreads();

    // warp 0 merges the 8 sorted 16-lists
    if (w == 0) {
        int p = 0;
        #pragma unroll 1
        for (int r = 0; r < TOPK; r++) {
            float hv = (lane < 8) ? cv[lane][p] : -FLT_MAX;
            int   hi = (lane < 8) ? ci[lane][p] : (1 << 30);
            float wv = hv; int wi = hi;
            #pragma unroll
            for (int o = 16; o; o >>= 1) {
                float ov = __shfl_xor_sync(0xffffffff, wv, o);
                int   oi = __shfl_xor_sync(0xffffffff, wi, o);
                if (ov > wv || (ov == wv && oi < wi)) { wv = ov; wi = oi; }
            }
            if (lane < 8 && wi == hi) p++;
            if (lane == 0) { rv_[r] = wv; ri_[r] = wi; }
        }
        __syncwarp();
        if (lane == 0) {
            float m = rv_[0];
            float e[TOPK], sum = 0.f;
            #pragma unroll
            for (int i = 0; i < TOPK; i++) { e[i] = expf(rv_[i] - m); sum += e[i]; }
            float inv = 1.f / sum;
            #pragma unroll
            for (int i = 0; i < TOPK; i++) {
                g_w[row * TOPK + i]   = e[i] * inv;
                g_idx[row * TOPK + i] = ri_[i];
            }
        }
    }
}

// ---------------------------------------------------------------------------
// K4: adj_sum = sum_r adjacency[r]   (float4 streaming, 201 MB read)
// ---------------------------------------------------------------------------
__global__ void k_adjsum(const float* __restrict__ adj) {
    const long long total4 = (long long)NN * NN / 4;
    const float4* a = (const float4*)adj;
    float4* o = (float4*)g_adjsum;
    for (long long i = (long long)blockIdx.x * blockDim.x + threadIdx.x;
         i < total4; i += (long long)gridDim.x * blockDim.x) {
        float4 acc = __ldcs(&a[i]);
        #pragma unroll
        for (int r = 1; r < RR; r++) {
            float4 vv = __ldcs(&a[i + (long long)r * total4]);
            acc.x += vv.x; acc.y += vv.y; acc.z += vv.z; acc.w += vv.w;
        }
        o[i] = acc;
    }
}

// ---------------------------------------------------------------------------
// K5: nei[row,:] = sum_k w[row,k] * adj_sum[idx[row,k], :]
// ---------------------------------------------------------------------------
__global__ void k_nei() {
    int row = blockIdx.x;
    __shared__ float w[TOPK];
    __shared__ int   id[TOPK];
    int tid = threadIdx.x;
    if (tid < TOPK) { w[tid] = g_w[row * TOPK + tid]; id[tid] = g_idx[row * TOPK + tid]; }
    __syncthreads();
    const float4* a4 = (const float4*)g_adjsum;
    float4* n4 = (float4*)g_nei;
    for (int c = tid; c < NN / 4; c += 256) {
        float4 acc = {0.f, 0.f, 0.f, 0.f};
        #pragma unroll
        for (int k = 0; k < TOPK; k++) {
            float4 vv = a4[(long long)id[k] * (NN / 4) + c];
            float wk = w[k];
            acc.x += wk * vv.x; acc.y += wk * vv.y; acc.z += wk * vv.z; acc.w += wk * vv.w;
        }
        n4[(long long)row * (NN / 4) + c] = acc;
    }
}

// ---------------------------------------------------------------------------
// K6: partial[z][m,d] = sum_{n in z-chunk} nei[m,n]*keys[n,d]
// BM=64, BN=64, BK=16, split-K=4, f32x2
// ---------------------------------------------------------------------------
__global__ void k_out_part() {
    __shared__ float Asd[16][132];
    __shared__ float Bs[16][68];
    int d0 = blockIdx.x * 64, m0 = blockIdx.y * 64;
    int kz = blockIdx.z;
    int t = threadIdx.x;
    int tx = t & 15, ty = t >> 4;
    int am = t >> 2, aq = t & 3;         // A loader
    int bk = t >> 4, bq = t & 15;        // B loader: 16 k-rows x 16 d-quads
    unsigned long long acc[4][2] = {};
    for (int k0 = kz * (NN / KSPLIT); k0 < (kz + 1) * (NN / KSPLIT); k0 += 16) {
        float4 av = *(const float4*)&g_nei[(long long)(m0 + am) * NN + k0 + aq * 4];
        float2 d0v = {av.x, av.x}, d1v = {av.y, av.y}, d2v = {av.z, av.z}, d3v = {av.w, av.w};
        *(float2*)&Asd[aq * 4 + 0][2 * am] = d0v;
        *(float2*)&Asd[aq * 4 + 1][2 * am] = d1v;
        *(float2*)&Asd[aq * 4 + 2][2 * am] = d2v;
        *(float2*)&Asd[aq * 4 + 3][2 * am] = d3v;
        float4 bv = *(const float4*)&g_keys[(long long)(k0 + bk) * D + d0 + bq * 4];
        *(float4*)&Bs[bk][bq * 4] = bv;
        __syncthreads();
        #pragma unroll
        for (int kk = 0; kk < 16; kk++) {
            ulonglong2 a01 = *(const ulonglong2*)&Asd[kk][ty * 8];
            ulonglong2 a23 = *(const ulonglong2*)&Asd[kk][ty * 8 + 4];
            ulonglong2 bb  = *(const ulonglong2*)&Bs[kk][tx * 4];
            FMA_F32X2(acc[0][0], a01.x, bb.x, acc[0][0]);
            FMA_F32X2(acc[0][1], a01.x, bb.y, acc[0][1]);
            FMA_F32X2(acc[1][0], a01.y, bb.x, acc[1][0]);
            FMA_F32X2(acc[1][1], a01.y, bb.y, acc[1][1]);
            FMA_F32X2(acc[2][0], a23.x, bb.x, acc[2][0]);
            FMA_F32X2(acc[2][1], a23.x, bb.y, acc[2][1]);
            FMA_F32X2(acc[3][0], a23.y, bb.x, acc[3][0]);
            FMA_F32X2(acc[3][1], a23.y, bb.y, acc[3][1]);
        }
        __syncthreads();
    }
    #pragma unroll
    for (int mm = 0; mm < 4; mm++) {
        float2 lo = *(float2*)&acc[mm][0];
        float2 hi = *(float2*)&acc[mm][1];
        float4 o = {lo.x, lo.y, hi.x, hi.y};
        *(float4*)&g_part[kz][(long long)(m0 + ty * 4 + mm) * D + d0 + tx * 4] = o;
    }
}

// K7: out = sum_z partial[z]
__global__ void k_reduce(float* __restrict__ out) {
    int i = blockIdx.x * blockDim.x + threadIdx.x;     // 49152 float4
    const float4* p0 = (const float4*)g_part[0];
    const float4* p1 = (const float4*)g_part[1];
    const float4* p2 = (const float4*)g_part[2];
    const float4* p3 = (const float4*)g_part[3];
    float4 a = p0[i], b = p1[i], c = p2[i], d = p3[i];
    float4 o = {a.x + b.x + c.x + d.x, a.y + b.y + c.y + d.y,
                a.z + b.z + c.z + d.z, a.w + b.w + c.w + d.w};
    ((float4*)out)[i] = o;
}

// ---------------------------------------------------------------------------
extern "C" void kernel_launch(void* const* d_in, const int* in_sizes, int n_in,
                              void* d_out, int out_size) {
    const float* pos = (const float*)d_in[0];   // (4,64,768) f32
    const float* kp  = (const float*)d_in[1];   // (2048,768) f32
    const float* adj = (const float*)d_in[2];   // (12,2048,2048) f32
    float* out = (float*)d_out;                 // (4,64,768) f32

    // Side stream + events: created once on first (non-captured) call.
    // Non-blocking so it doesn't implicitly sync with the legacy stream.
    static cudaStream_t sB = nullptr;
    static cudaEvent_t eFork = nullptr, eJoin = nullptr;
    if (!sB) {
        cudaStreamCreateWithFlags(&sB, cudaStreamNonBlocking);
        cudaEventCreateWithFlags(&eFork, cudaEventDisableTiming);
        cudaEventCreateWithFlags(&eJoin, cudaEventDisableTiming);
    }

    // fork: chain B (normalize -> scores -> topk) on side stream
    cudaEventRecord(eFork, 0);
    cudaStreamWaitEvent(sB, eFork, 0);
    k_normalize<<<NN, 256, 0, sB>>>(kp);
    k_scores<<<dim3(NN / 64, BP / 64), 256, 0, sB>>>(pos);
    k_topk<<<BP, 256, 0, sB>>>();
    cudaEventRecord(eJoin, sB);

    // chain A: dominant HBM kernel on main stream (overlaps with chain B)
    k_adjsum<<<1184, 256>>>(adj);

    // join, then dependent tail
    cudaStreamWaitEvent(0, eJoin, 0);
    k_nei<<<BP, 256>>>();
    k_out_part<<<dim3(D / 64, BP / 64, KSPLIT), 256>>>();
    k_reduce<<<BP * D / 4 / 256, 256>>>(out);
}

// round 7
// speedup vs baseline: 1.6268x; 1.6268x over previous
#include <cuda_runtime.h>
#include <float.h>

#define NB    4
#define NP    64
#define BP    256           // NB*NP query rows
#define D     768
#define NN    2048
#define RR    12
#define TOPK  16
#define KSPLIT 4
#define ADJ_BLOCKS 1184

// ---- scratch (static __device__, no allocations) ----
__device__ float g_rnorm[NN];             // 1/||keys_param row||
__device__ float g_scores[BP * NN];       // scores               2.0 MB
__device__ int   g_idx[BP * TOPK];
__device__ float g_w[BP * TOPK];
__device__ float g_adjsum[NN * NN];       // sum_r adjacency     16.8 MB
__device__ float g_nei[BP * NN];          //                      2.0 MB
__device__ float g_part[KSPLIT][BP * D];  // split-K partials     3.1 MB

#define FMA_F32X2(d, a, b, c) \
    asm("fma.rn.f32x2 %0, %1, %2, %3;" : "=l"(d) : "l"(a), "l"(b), "l"(c))

// ---------------------------------------------------------------------------
// K1: fused adj_sum (sum_r adjacency, 201 MB stream) + key inverse norms.
// Blocks [0, ADJ_BLOCKS) do adjsum (2 float4 sites per grid-stride step for
// ~24 outstanding LDGs); blocks [ADJ_BLOCKS, ADJ_BLOCKS+16) do rnorm.
// ---------------------------------------------------------------------------
__global__ void k_adjsum_rnorm(const float* __restrict__ adj,
                               const float* __restrict__ kp) {
    if (blockIdx.x >= ADJ_BLOCKS) {
        // ---- rnorm: 16 blocks x 8 warps x 16 rows = 2048 rows ----
        int bb = blockIdx.x - ADJ_BLOCKS;
        int w = threadIdx.x >> 5, lane = threadIdx.x & 31;
        for (int rr = 0; rr < 16; rr++) {
            int row = bb * 128 + rr * 8 + w;
            const float* src = kp + (long long)row * D;
            float ss = 0.f;
            #pragma unroll
            for (int i = 0; i < D / 32; i++) { float v = src[i * 32 + lane]; ss += v * v; }
            #pragma unroll
            for (int o = 16; o; o >>= 1) ss += __shfl_xor_sync(0xffffffff, ss, o);
            if (lane == 0) g_rnorm[row] = rsqrtf(ss + 1e-12f);
        }
        return;
    }
    const long long t4 = (long long)NN * NN / 4;
    const long long S = (long long)ADJ_BLOCKS * 256;
    const float4* a = (const float4*)adj;
    float4* o = (float4*)g_adjsum;
    for (long long i = (long long)blockIdx.x * 256 + threadIdx.x; i < t4; i += 2 * S) {
        long long j = i + S;
        bool h2 = j < t4;
        float4 acc0 = __ldcs(&a[i]);
        float4 acc1 = h2 ? __ldcs(&a[j]) : make_float4(0.f, 0.f, 0.f, 0.f);
        #pragma unroll
        for (int r = 1; r < RR; r++) {
            float4 v0 = __ldcs(&a[i + (long long)r * t4]);
            float4 v1 = h2 ? __ldcs(&a[j + (long long)r * t4]) : make_float4(0.f, 0.f, 0.f, 0.f);
            acc0.x += v0.x; acc0.y += v0.y; acc0.z += v0.z; acc0.w += v0.w;
            acc1.x += v1.x; acc1.y += v1.y; acc1.z += v1.z; acc1.w += v1.w;
        }
        o[i] = acc0;
        if (h2) o[j] = acc1;
    }
}

// ---------------------------------------------------------------------------
// K2: scores[m,n] = sum_d pos[m,d]*kp[n,d]*rnorm[n]  (NT), f32x2 FFMA2
// BM=64, BN=64, BK=16, 256 thr, 4x4 thread tile, A duplicated in smem
// ---------------------------------------------------------------------------
__global__ void k_scores(const float* __restrict__ pos, const float* __restrict__ kp) {
    __shared__ float Asd[16][132];   // duplicated pairs: Asd[k][2m]=Asd[k][2m+1]=A[m][k]
    __shared__ float Bs[16][68];
    int m0 = blockIdx.y * 64, n0 = blockIdx.x * 64;
    int t = threadIdx.x;
    int tx = t & 15, ty = t >> 4;        // tx: n-quad, ty: m-quad
    int am = t >> 2, aq = t & 3;         // loader mapping (64 rows x 4 quads)
    float brn = g_rnorm[n0 + am];        // B row scale (row = n0+am)
    unsigned long long acc[4][2] = {};
    for (int k0 = 0; k0 < D; k0 += 16) {
        float4 av = *(const float4*)&pos[(long long)(m0 + am) * D + k0 + aq * 4];
        float2 d0 = {av.x, av.x}, d1 = {av.y, av.y}, d2 = {av.z, av.z}, d3 = {av.w, av.w};
        *(float2*)&Asd[aq * 4 + 0][2 * am] = d0;
        *(float2*)&Asd[aq * 4 + 1][2 * am] = d1;
        *(float2*)&Asd[aq * 4 + 2][2 * am] = d2;
        *(float2*)&Asd[aq * 4 + 3][2 * am] = d3;
        float4 bv = *(const float4*)&kp[(long long)(n0 + am) * D + k0 + aq * 4];
        Bs[aq * 4 + 0][am] = bv.x * brn;
        Bs[aq * 4 + 1][am] = bv.y * brn;
        Bs[aq * 4 + 2][am] = bv.z * brn;
        Bs[aq * 4 + 3][am] = bv.w * brn;
        __syncthreads();
        #pragma unroll
        for (int kk = 0; kk < 16; kk++) {
            ulonglong2 a01 = *(const ulonglong2*)&Asd[kk][ty * 8];
            ulonglong2 a23 = *(const ulonglong2*)&Asd[kk][ty * 8 + 4];
            ulonglong2 bb  = *(const ulonglong2*)&Bs[kk][tx * 4];
            FMA_F32X2(acc[0][0], a01.x, bb.x, acc[0][0]);
            FMA_F32X2(acc[0][1], a01.x, bb.y, acc[0][1]);
            FMA_F32X2(acc[1][0], a01.y, bb.x, acc[1][0]);
            FMA_F32X2(acc[1][1], a01.y, bb.y, acc[1][1]);
            FMA_F32X2(acc[2][0], a23.x, bb.x, acc[2][0]);
            FMA_F32X2(acc[2][1], a23.x, bb.y, acc[2][1]);
            FMA_F32X2(acc[3][0], a23.y, bb.x, acc[3][0]);
            FMA_F32X2(acc[3][1], a23.y, bb.y, acc[3][1]);
        }
        __syncthreads();
    }
    #pragma unroll
    for (int mm = 0; mm < 4; mm++) {
        float2 lo = *(float2*)&acc[mm][0];
        float2 hi = *(float2*)&acc[mm][1];
        float4 o = {lo.x, lo.y, hi.x, hi.y};
        *(float4*)&g_scores[(long long)(m0 + ty * 4 + mm) * NN + n0 + tx * 4] = o;
    }
}

// ---------------------------------------------------------------------------
// K3: block-per-row top-16 + softmax.
// Each warp: lane-sort-8 (Batcher) + 16 shfl-argmax pops -> warp top16.
// Warp 0 merges 8x16 candidates. Ties -> smaller index (matches lax.top_k).
// ---------------------------------------------------------------------------
__global__ void k_topk() {
    int row = blockIdx.x;
    int w = threadIdx.x >> 5, lane = threadIdx.x & 31;
    __shared__ float cv[8][TOPK];
    __shared__ int   ci[8][TOPK];
    __shared__ float rv_[TOPK];
    __shared__ int   ri_[TOPK];

    const float4* src = (const float4*)(g_scores + (long long)row * NN);
    float4 x = src[w * 64 + lane];
    float4 y = src[w * 64 + 32 + lane];
    int b0 = (w * 64 + lane) * 4, b1 = (w * 64 + 32 + lane) * 4;
    float v[8]  = {x.x, x.y, x.z, x.w, y.x, y.y, y.z, y.w};
    int   id[8] = {b0, b0 + 1, b0 + 2, b0 + 3, b1, b1 + 1, b1 + 2, b1 + 3};

    // descending sort, tie -> smaller index (19-CE Batcher network)
    #define CE(i, j) do {                                                 \
        float _av = v[i], _bv = v[j]; int _ai = id[i], _bi = id[j];       \
        bool _sw = (_bv > _av) || (_bv == _av && _bi < _ai);              \
        v[i]  = _sw ? _bv : _av;  id[i] = _sw ? _bi : _ai;                \
        v[j]  = _sw ? _av : _bv;  id[j] = _sw ? _ai : _bi;                \
    } while (0)
    CE(0,1); CE(2,3); CE(4,5); CE(6,7);
    CE(0,2); CE(1,3); CE(4,6); CE(5,7);
    CE(1,2); CE(5,6);
    CE(0,4); CE(1,5); CE(2,6); CE(3,7);
    CE(2,4); CE(3,5);
    CE(1,2); CE(3,4); CE(5,6);
    #undef CE

    // 16 pops: warp argmax over lane heads
    #pragma unroll 1
    for (int r = 0; r < TOPK; r++) {
        float wv = v[0]; int wi = id[0];
        #pragma unroll
        for (int o = 16; o; o >>= 1) {
            float ov = __shfl_xor_sync(0xffffffff, wv, o);
            int   oi = __shfl_xor_sync(0xffffffff, wi, o);
            if (ov > wv || (ov == wv && oi < wi)) { wv = ov; wi = oi; }
        }
        if (wi == id[0]) {                       // this lane owned the winner
            #pragma unroll
            for (int q = 0; q < 7; q++) { v[q] = v[q + 1]; id[q] = id[q + 1]; }
            v[7] = -FLT_MAX; id[7] = 1 << 30;
        }
        if (lane == 0) { cv[w][r] = wv; ci[w][r] = wi; }
    }
    __syncthreads();

    // warp 0 merges the 8 sorted 16-lists
    if (w == 0) {
        int p = 0;
        #pragma unroll 1
        for (int r = 0; r < TOPK; r++) {
            float hv = (lane < 8) ? cv[lane][p] : -FLT_MAX;
            int   hi = (lane < 8) ? ci[lane][p] : (1 << 30);
            float wv = hv; int wi = hi;
            #pragma unroll
            for (int o = 16; o; o >>= 1) {
                float ov = __shfl_xor_sync(0xffffffff, wv, o);
                int   oi = __shfl_xor_sync(0xffffffff, wi, o);
                if (ov > wv || (ov == wv && oi < wi)) { wv = ov; wi = oi; }
            }
            if (lane < 8 && wi == hi) p++;
            if (lane == 0) { rv_[r] = wv; ri_[r] = wi; }
        }
        __syncwarp();
        if (lane == 0) {
            float m = rv_[0];
            float e[TOPK], sum = 0.f;
            #pragma unroll
            for (int i = 0; i < TOPK; i++) { e[i] = expf(rv_[i] - m); sum += e[i]; }
            float inv = 1.f / sum;
            #pragma unroll
            for (int i = 0; i < TOPK; i++) {
                g_w[row * TOPK + i]   = e[i] * inv;
                g_idx[row * TOPK + i] = ri_[i];
            }
        }
    }
}

// ---------------------------------------------------------------------------
// K5: nei[row,:] = sum_k w[row,k] * adj_sum[idx[row,k], :]
// ---------------------------------------------------------------------------
__global__ void k_nei() {
    int row = blockIdx.x;
    __shared__ float w[TOPK];
    __shared__ int   id[TOPK];
    int tid = threadIdx.x;
    if (tid < TOPK) { w[tid] = g_w[row * TOPK + tid]; id[tid] = g_idx[row * TOPK + tid]; }
    __syncthreads();
    const float4* a4 = (const float4*)g_adjsum;
    float4* n4 = (float4*)g_nei;
    for (int c = tid; c < NN / 4; c += 256) {
        float4 acc = {0.f, 0.f, 0.f, 0.f};
        #pragma unroll
        for (int k = 0; k < TOPK; k++) {
            float4 vv = a4[(long long)id[k] * (NN / 4) + c];
            float wk = w[k];
            acc.x += wk * vv.x; acc.y += wk * vv.y; acc.z += wk * vv.z; acc.w += wk * vv.w;
        }
        n4[(long long)row * (NN / 4) + c] = acc;
    }
}

// ---------------------------------------------------------------------------
// K6: partial[z][m,d] = sum_{n in z-chunk} nei[m,n]*kp[n,d]*rnorm[n]
// BM=64, BN=64, BK=16, split-K=4, f32x2
// ---------------------------------------------------------------------------
__global__ void k_out_part(const float* __restrict__ kp) {
    __shared__ float Asd[16][132];
    __shared__ float Bs[16][68];
    int d0 = blockIdx.x * 64, m0 = blockIdx.y * 64;
    int kz = blockIdx.z;
    int t = threadIdx.x;
    int tx = t & 15, ty = t >> 4;
    int am = t >> 2, aq = t & 3;         // A loader
    int bk = t >> 4, bq = t & 15;        // B loader: 16 k-rows x 16 d-quads
    unsigned long long acc[4][2] = {};
    for (int k0 = kz * (NN / KSPLIT); k0 < (kz + 1) * (NN / KSPLIT); k0 += 16) {
        float4 av = *(const float4*)&g_nei[(long long)(m0 + am) * NN + k0 + aq * 4];
        float2 d0v = {av.x, av.x}, d1v = {av.y, av.y}, d2v = {av.z, av.z}, d3v = {av.w, av.w};
        *(float2*)&Asd[aq * 4 + 0][2 * am] = d0v;
        *(float2*)&Asd[aq * 4 + 1][2 * am] = d1v;
        *(float2*)&Asd[aq * 4 + 2][2 * am] = d2v;
        *(float2*)&Asd[aq * 4 + 3][2 * am] = d3v;
        float brn = g_rnorm[k0 + bk];
        float4 bv = *(const float4*)&kp[(long long)(k0 + bk) * D + d0 + bq * 4];
        bv.x *= brn; bv.y *= brn; bv.z *= brn; bv.w *= brn;
        *(float4*)&Bs[bk][bq * 4] = bv;
        __syncthreads();
        #pragma unroll
        for (int kk = 0; kk < 16; kk++) {
            ulonglong2 a01 = *(const ulonglong2*)&Asd[kk][ty * 8];
            ulonglong2 a23 = *(const ulonglong2*)&Asd[kk][ty * 8 + 4];
            ulonglong2 bb  = *(const ulonglong2*)&Bs[kk][tx * 4];
            FMA_F32X2(acc[0][0], a01.x, bb.x, acc[0][0]);
            FMA_F32X2(acc[0][1], a01.x, bb.y, acc[0][1]);
            FMA_F32X2(acc[1][0], a01.y, bb.x, acc[1][0]);
            FMA_F32X2(acc[1][1], a01.y, bb.y, acc[1][1]);
            FMA_F32X2(acc[2][0], a23.x, bb.x, acc[2][0]);
            FMA_F32X2(acc[2][1], a23.x, bb.y, acc[2][1]);
            FMA_F32X2(acc[3][0], a23.y, bb.x, acc[3][0]);
            FMA_F32X2(acc[3][1], a23.y, bb.y, acc[3][1]);
        }
        __syncthreads();
    }
    #pragma unroll
    for (int mm = 0; mm < 4; mm++) {
        float2 lo = *(float2*)&acc[mm][0];
        float2 hi = *(float2*)&acc[mm][1];
        float4 o = {lo.x, lo.y, hi.x, hi.y};
        *(float4*)&g_part[kz][(long long)(m0 + ty * 4 + mm) * D + d0 + tx * 4] = o;
    }
}

// K7: out = sum_z partial[z]
__global__ void k_reduce(float* __restrict__ out) {
    int i = blockIdx.x * blockDim.x + threadIdx.x;     // 49152 float4
    const float4* p0 = (const float4*)g_part[0];
    const float4* p1 = (const float4*)g_part[1];
    const float4* p2 = (const float4*)g_part[2];
    const float4* p3 = (const float4*)g_part[3];
    float4 a = p0[i], b = p1[i], c = p2[i], d = p3[i];
    float4 o = {a.x + b.x + c.x + d.x, a.y + b.y + c.y + d.y,
                a.z + b.z + c.z + d.z, a.w + b.w + c.w + d.w};
    ((float4*)out)[i] = o;
}

// ---------------------------------------------------------------------------
extern "C" void kernel_launch(void* const* d_in, const int* in_sizes, int n_in,
                              void* d_out, int out_size) {
    const float* pos = (const float*)d_in[0];   // (4,64,768) f32
    const float* kp  = (const float*)d_in[1];   // (2048,768) f32
    const float* adj = (const float*)d_in[2];   // (12,2048,2048) f32
    float* out = (float*)d_out;                 // (4,64,768) f32

    k_adjsum_rnorm<<<ADJ_BLOCKS + 16, 256>>>(adj, kp);
    k_scores<<<dim3(NN / 64, BP / 64), 256>>>(pos, kp);
    k_topk<<<BP, 256>>>();
    k_nei<<<BP, 256>>>();
    k_out_part<<<dim3(D / 64, BP / 64, KSPLIT), 256>>>(kp);
    k_reduce<<<BP * D / 4 / 256, 256>>>(out);
}